// round 13
// baseline (speedup 1.0000x reference)
#include <cuda_runtime.h>
#include <cuda_fp16.h>
#include <cstdint>

// ---------------------------------------------------------------------------
// out = concat( relu(A@relu(A@F)), A@(A@G) ), A:[8192,8192] f32, F,G:[8192,64]
// Per layer: fused GEMM C[8192,128] = A @ Bt^T, relu on cols [0,64).
// fp16 mma.m16n8k16 (mainloop at the legacy-HMMA issue floor, rt~17.3).
// Round 13: pack kernel removed — layer-1 producers synthesize the B tile
// from F/G (LDG + cvt + STS) directly into smem; layer 2 unchanged (cp.async
// from bt2 + PDL). Epilogues from R12.
// ---------------------------------------------------------------------------

#define NN      8192
#define NB      128
#define MT      64              // M rows per CTA -> 128 CTAs
#define KT      32              // K per stage
#define STAGES  8
#define KIT     (NN / KT)       // 256
#define A_PITCH 160             // bytes per A smem row (fp32 k32 + pad)
#define B_PITCH 64              // bytes per B smem row (fp16 k32)
#define A_STG_B (64 * A_PITCH)  // 10240
#define B_STG_B (128 * B_PITCH) // 8192
#define STG_B   (A_STG_B + B_STG_B)        // 18432
#define SMEM_BYTES (STAGES * STG_B)        // 147456
#define STG_PITCH 136           // staging bytes per col (64 rows fp16 + pad)

__device__ __half g_bth2[NB * NN];   // layer-1 out (x2^6) = layer-2 B

__device__ __forceinline__ uint32_t smem_u32(const void* p) {
    uint32_t a;
    asm("{ .reg .u64 t; cvta.to.shared.u64 t, %1; cvt.u32.u64 %0, t; }"
        : "=r"(a) : "l"(p));
    return a;
}

// pack two fp32 -> fp16x2 (lo = first arg)
__device__ __forceinline__ uint32_t pack_h2(float lo, float hi) {
    uint32_t d;
    asm("cvt.rn.f16x2.f32 %0, %1, %2;" : "=r"(d) : "f"(hi), "f"(lo));
    return d;
}

#define GDC_LAUNCH() asm volatile("griddepcontrol.launch_dependents;" ::: "memory")
#define GDC_WAIT()   asm volatile("griddepcontrol.wait;" ::: "memory")

#define CP_ASYNC16(dst, src) \
    asm volatile("cp.async.cg.shared.global [%0], [%1], 16;" \
                 :: "r"(dst), "l"(src) : "memory")

#define MBAR_INIT(addr, cnt) \
    asm volatile("mbarrier.init.shared.b64 [%0], %1;" :: "r"(addr), "r"(cnt) : "memory")
#define MBAR_ARRIVE_REL(addr) \
    asm volatile("mbarrier.arrive.release.cta.shared::cta.b64 _, [%0];" \
                 :: "r"(addr) : "memory")
#define CP_ASYNC_MBAR_ARRIVE(addr) \
    asm volatile("cp.async.mbarrier.arrive.noinc.shared::cta.b64 [%0];" \
                 :: "r"(addr) : "memory")

#define MBAR_WAIT(addr, parity) do {                                          \
    uint32_t _mb = (addr); uint32_t _ph = (parity); uint32_t _done;           \
    asm volatile("{\n\t.reg .pred p;\n\t"                                     \
        "mbarrier.try_wait.parity.acquire.cta.shared::cta.b64 p, [%1], %2;\n\t"\
        "selp.b32 %0, 1, 0, p;\n\t}"                                          \
        : "=r"(_done) : "r"(_mb), "r"(_ph) : "memory");                       \
    if (!_done) {                                                             \
        asm volatile("{\n\t.reg .pred P1;\n\t"                                \
            "WL_%=:\n\t"                                                      \
            "mbarrier.try_wait.parity.acquire.cta.shared::cta.b64 P1, [%0], %1, 0x989680;\n\t" \
            "@P1 bra.uni WD_%=;\n\t"                                          \
            "bra.uni WL_%=;\n\t"                                              \
            "WD_%=:\n\t}"                                                     \
            :: "r"(_mb), "r"(_ph) : "memory");                                \
    }                                                                         \
} while (0)

__device__ __forceinline__ void mma_f16(float* c, const uint32_t* a,
                                        uint32_t b0, uint32_t b1) {
    asm volatile(
        "mma.sync.aligned.m16n8k16.row.col.f32.f16.f16.f32 "
        "{%0,%1,%2,%3}, {%4,%5,%6,%7}, {%8,%9}, {%0,%1,%2,%3};"
        : "+f"(c[0]), "+f"(c[1]), "+f"(c[2]), "+f"(c[3])
        : "r"(a[0]), "r"(a[1]), "r"(a[2]), "r"(a[3]), "r"(b0), "r"(b1));
}

// ---------------------------------------------------------------------------
// Fused layer GEMM.
// Layer 1: Fin/Gin non-null, Bt==null -> producers synthesize B from F/G;
//          outT written (fp16, chunk-permuted, x2^6 folded into scale).
// Layer 2: Bt non-null -> cp.async B path; outR written (f32 row-major).
// ---------------------------------------------------------------------------
__global__ void __launch_bounds__(256, 1)
gemm_layer(const float* __restrict__ A, const __half* __restrict__ Bt,
           const float* __restrict__ Fin, const float* __restrict__ Gin,
           __half* __restrict__ outT, float* __restrict__ outR, float scale) {
    extern __shared__ char smem[];
    __shared__ __align__(8) uint64_t mbar[2 * STAGES];

    const int tid  = threadIdx.x;
    const int lane = tid & 31;
    const int w    = tid >> 5;
    const int m0   = blockIdx.x * MT;
    const uint32_t sbase = smem_u32(smem);
    const uint32_t mb    = smem_u32(mbar);
    const int r4 = lane >> 2;
    const int c4 = lane & 3;

    if (tid == 0) {
        #pragma unroll
        for (int s = 0; s < STAGES; s++) {
            MBAR_INIT(mb + 8 * s, 256);                 // full: 128 cp + 128 sts
            MBAR_INIT(mb + 8 * (STAGES + s), 128);      // empty: 128 consumers
        }
    }
    __syncthreads();
    GDC_LAUNCH();          // allow next kernel's CTAs to start as SMs free up

    if (w >= 4) {
        // ================= producers (warps 4-7) =================
        const int t = tid - 128;

        auto issueA = [&](int it) {
            const int k0 = it * KT;
            const uint32_t abase = sbase + (uint32_t)(it & (STAGES - 1)) * STG_B;
            #pragma unroll
            for (int j = 0; j < 4; j++) {               // A: 512 x 16B (fp32)
                int ch = t + 128 * j;
                int row = ch >> 3, cc = ch & 7;
                const float* src = A + (size_t)(m0 + row) * NN + k0 + cc * 4;
                CP_ASYNC16(abase + (uint32_t)(row * A_PITCH + cc * 16), src);
            }
        };
        auto issueB = [&](int it) {                     // layer 2: cp.async
            const int k0 = it * KT;
            const uint32_t bbase = sbase + (uint32_t)(it & (STAGES - 1)) * STG_B
                                   + A_STG_B;
            #pragma unroll
            for (int j = 0; j < 4; j++) {               // B: 512 x 16B (fp16)
                int ch = t + 128 * j;
                int col = ch >> 2, q = ch & 3;
                const __half* src = Bt + (size_t)col * NN + k0 + q * 8;
                CP_ASYNC16(bbase + (uint32_t)(col * B_PITCH + q * 16), src);
            }
        };
        // layer 1: synthesize B tile from F/G. Thread t = column t.
        // word p = 4Q+i holds original k-pair j = 4i+Q (k = k0+2j), matching
        // the consumer's uint4 component mapping.
        const float* bsrc = (t < 64) ? (Fin ? Fin + t : nullptr)
                                     : (Gin ? Gin + (t - 64) : nullptr);
        auto genB = [&](int it) {
            const int k0 = it * KT;
            const uint32_t bbase = sbase + (uint32_t)(it & (STAGES - 1)) * STG_B
                                   + A_STG_B + (uint32_t)(t * B_PITCH);
            #pragma unroll
            for (int Q = 0; Q < 4; Q++) {
                uint32_t wr[4];
                #pragma unroll
                for (int i = 0; i < 4; i++) {
                    int k = k0 + 2 * Q + 8 * i;
                    float v0 = __ldg(bsrc + (size_t)k * 64);
                    float v1 = __ldg(bsrc + (size_t)(k + 1) * 64);
                    wr[i] = pack_h2(v0, v1);
                }
                asm volatile("st.shared.v4.b32 [%0], {%1,%2,%3,%4};"
                             :: "r"(bbase + (uint32_t)(Q * 16)),
                                "r"(wr[0]), "r"(wr[1]), "r"(wr[2]), "r"(wr[3])
                             : "memory");
            }
        };

        if (Bt) {
            // -------- layer 2: A-prefetch, PDL wait, then B --------
            issueA(0); issueA(1); issueA(2);
            GDC_WAIT();                     // previous kernel's bt2 visible
            #pragma unroll
            for (int it = 0; it < 3; it++) {
                issueB(it);
                MBAR_ARRIVE_REL(mb + 8 * it);           // count filler
                CP_ASYNC_MBAR_ARRIVE(mb + 8 * it);
            }
            for (int it = 3; it < KIT; it++) {
                const int s = it & (STAGES - 1);
                const int r = it >> 3;
                if (r > 0) MBAR_WAIT(mb + 8 * (STAGES + s), (r - 1) & 1);
                issueA(it);
                issueB(it);
                MBAR_ARRIVE_REL(mb + 8 * s);
                CP_ASYNC_MBAR_ARRIVE(mb + 8 * s);
            }
        } else {
            // -------- layer 1: B synthesized from F/G --------
            for (int it = 0; it < KIT; it++) {
                const int s = it & (STAGES - 1);
                const int r = it >> 3;
                if (r > 0) MBAR_WAIT(mb + 8 * (STAGES + s), (r - 1) & 1);
                issueA(it);
                genB(it);
                MBAR_ARRIVE_REL(mb + 8 * s);            // covers STS
                CP_ASYNC_MBAR_ARRIVE(mb + 8 * s);       // covers A cp.async
            }
        }
        return;
    }

    // ================= MMA warps (0-3): 32 rows x 64 cols =================
    const int wm = w >> 1;
    const int wn = w & 1;

    float acc[2][8][4];
    #pragma unroll
    for (int mi = 0; mi < 2; mi++)
        #pragma unroll
        for (int ni = 0; ni < 8; ni++)
            #pragma unroll
            for (int j = 0; j < 4; j++) acc[mi][ni][j] = 0.f;

    const uint32_t aoff = (uint32_t)((wm * 32 + r4) * A_PITCH + 8 * c4);
    const uint32_t boff = (uint32_t)((wn * 64 + r4) * B_PITCH + 16 * c4);

    // A half h (k16) of stage s -> 8 fp16x2 regs (scaled x2^13)
    auto loadA = [&](int s, int h, uint32_t (&aH)[4][2]) {
        const uint32_t off = (uint32_t)s * STG_B + aoff + (uint32_t)(h * 64);
        #pragma unroll
        for (int g = 0; g < 4; g++) {
            float2 lo = *(const float2*)(smem + off + g * 8 * A_PITCH);
            float2 hi = *(const float2*)(smem + off + g * 8 * A_PITCH + 32);
            aH[g][0] = pack_h2(lo.x * 8192.f, lo.y * 8192.f);
            aH[g][1] = pack_h2(hi.x * 8192.f, hi.y * 8192.f);
        }
    };

    // full-stage B -> 8 x uint4 (x=h0b0, y=h0b1, z=h1b0, w=h1b1)
    auto loadB = [&](int s, uint4 (&bS)[8]) {
        const char* base = smem + (size_t)s * STG_B + A_STG_B + boff;
        #pragma unroll
        for (int g = 0; g < 8; g++)
            bS[g] = *(const uint4*)(base + g * 8 * B_PITCH);
    };

    auto mma_half = [&](uint32_t (&aH)[4][2], uint4 (&bS)[8], int h) {
        #pragma unroll
        for (int ni = 0; ni < 8; ni++) {
            uint32_t b0 = h ? bS[ni].z : bS[ni].x;
            uint32_t b1 = h ? bS[ni].w : bS[ni].y;
            {
                uint32_t af[4] = { aH[0][0], aH[1][0], aH[0][1], aH[1][1] };
                mma_f16(acc[0][ni], af, b0, b1);
            }
            {
                uint32_t af[4] = { aH[2][0], aH[3][0], aH[2][1], aH[3][1] };
                mma_f16(acc[1][ni], af, b0, b1);
            }
        }
    };

    uint32_t A0[4][2], A1[4][2];
    uint4    Bb[2][8];

    MBAR_WAIT(mb + 0, 0);
    loadB(0, Bb[0]);
    loadA(0, 0, A0);

    #pragma unroll 2
    for (int it = 0; it < KIT; it++) {
        const int s = it & (STAGES - 1);
        const int cur = it & 1, nxt = cur ^ 1;

        loadA(s, 1, A1);
        mma_half(A0, Bb[cur], 0);

        if (it + 1 < KIT) {
            const int s1 = (it + 1) & (STAGES - 1);
            MBAR_WAIT(mb + 8 * s1, ((it + 1) >> 3) & 1);
            loadB(s1, Bb[nxt]);
            loadA(s1, 0, A0);
        }
        mma_half(A1, Bb[cur], 1);

        MBAR_ARRIVE_REL(mb + 8 * (STAGES + s));
    }

    // ---- epilogue ----
    const int rBase = m0 + wm * 32 + r4;
    const int cBase = wn * 64 + c4 * 2;

    if (outT) {
        // staged transposed store: smem [col][row] (pitch 136B), then each
        // warp streams 32 cols as coalesced 4B lane stores.
        asm volatile("bar.sync 1, 128;" ::: "memory");   // all MMAs done
        #pragma unroll
        for (int mi = 0; mi < 2; mi++) {
            #pragma unroll
            for (int ni = 0; ni < 8; ni++) {
                #pragma unroll
                for (int j = 0; j < 4; j++) {
                    int row_l = wm * 32 + r4 + mi * 16 + (j >> 1) * 8;
                    int col   = cBase + ni * 8 + (j & 1);
                    float v = acc[mi][ni][j] * scale;
                    if (col < 64) v = fmaxf(v, 0.0f);
                    *(__half*)(smem + col * STG_PITCH + row_l * 2) =
                        __float2half_rn(v);
                }
            }
        }
        asm volatile("bar.sync 1, 128;" ::: "memory");
        const int b  = lane >> 4;
        const int jj = lane & 15;
        const int q  = ((jj & 3) << 2) | (jj >> 2);     // kperm2 chunk pos
        #pragma unroll
        for (int c = 0; c < 32; c++) {
            int col = w * 32 + c;
            uint32_t v = *(const uint32_t*)(smem + col * STG_PITCH + lane * 4);
            *(uint32_t*)((char*)outT +
                2 * ((size_t)col * NN + m0 + b * 32 + 2 * q)) = v;
        }
    } else {
        #pragma unroll
        for (int mi = 0; mi < 2; mi++) {
            #pragma unroll
            for (int ni = 0; ni < 8; ni++) {
                #pragma unroll
                for (int jh = 0; jh < 2; jh++) {
                    int row = rBase + mi * 16 + jh * 8;
                    int col = cBase + ni * 8;
                    float v0 = acc[mi][ni][2 * jh]     * scale;
                    float v1 = acc[mi][ni][2 * jh + 1] * scale;
                    if (col < 64) { v0 = fmaxf(v0, 0.f); v1 = fmaxf(v1, 0.f); }
                    *(float2*)(outR + (size_t)row * NB + col) =
                        make_float2(v0, v1);
                }
            }
        }
    }
}

// ---------------------------------------------------------------------------
extern "C" void kernel_launch(void* const* d_in, const int* in_sizes, int n_in,
                              void* d_out, int out_size) {
    (void)in_sizes; (void)n_in; (void)out_size;
    const float* A = (const float*)d_in[0];
    const float* F = (const float*)d_in[1];
    const float* G = (const float*)d_in[2];
    float* out = (float*)d_out;

    __half* bt2 = nullptr;
    cudaGetSymbolAddress((void**)&bt2, g_bth2);

    cudaFuncSetAttribute(gemm_layer,
                         cudaFuncAttributeMaxDynamicSharedMemorySize, SMEM_BYTES);

    // layer 1: acc = (2^13 A) @ B(F||G) ; store fp16( acc * 2^-7 ) = 2^6*(A@B)
    gemm_layer<<<NN / MT, 256, SMEM_BYTES>>>(A, (const __half*)nullptr, F, G,
                                             bt2, (float*)nullptr, 0.0078125f);

    // layer 2 (PDL-overlapped): acc = (2^13 A) @ (2^6 h) ; out = acc * 2^-19
    cudaLaunchAttribute at[1];
    at[0].id = cudaLaunchAttributeProgrammaticStreamSerialization;
    at[0].val.programmaticStreamSerializationAllowed = 1;

    cudaLaunchConfig_t cfg = {};
    cfg.gridDim = dim3(NN / MT);
    cfg.blockDim = dim3(256);
    cfg.dynamicSmemBytes = SMEM_BYTES;
    cfg.stream = 0;
    cfg.attrs = at;
    cfg.numAttrs = 1;

    cudaError_t e2 = cudaLaunchKernelEx(&cfg, gemm_layer,
                                        A, (const __half*)bt2,
                                        (const float*)nullptr,
                                        (const float*)nullptr,
                                        (__half*)nullptr, out,
                                        1.0f / 524288.0f);
    if (e2 != cudaSuccess)
        gemm_layer<<<NN / MT, 256, SMEM_BYTES>>>(A, bt2,
                                                 (const float*)nullptr,
                                                 (const float*)nullptr,
                                                 (__half*)nullptr, out,
                                                 1.0f / 524288.0f);
}

// round 14
// speedup vs baseline: 1.6098x; 1.6098x over previous
#include <cuda_runtime.h>
#include <cuda_fp16.h>
#include <cstdint>

// ---------------------------------------------------------------------------
// out = concat( relu(A@relu(A@F)), A@(A@G) ), A:[8192,8192] f32, F,G:[8192,64]
// Per layer: fused GEMM C[8192,128] = A @ Bt^T, relu on cols [0,64).
// fp16 mma.m16n8k16. R14: 8 consumer warps (2/SMSP, 32x32 tiles — N-split so
// crossbar traffic is unchanged vs R7/R12) + 4 cp.async producer warps.
// Pack kernel + PDL + staged transposed epilogue as in R12.
// ---------------------------------------------------------------------------

#define NN      8192
#define NB      128
#define MT      64              // M rows per CTA -> 128 CTAs
#define KT      32              // K per stage
#define STAGES  8
#define KIT     (NN / KT)       // 256
#define A_PITCH 160             // bytes per A smem row (fp32 k32 + pad)
#define B_PITCH 64              // bytes per B smem row (fp16 k32)
#define A_STG_B (64 * A_PITCH)  // 10240
#define B_STG_B (128 * B_PITCH) // 8192
#define STG_B   (A_STG_B + B_STG_B)        // 18432
#define SMEM_BYTES (STAGES * STG_B)        // 147456
#define STG_PITCH 136           // staging bytes per col (64 rows fp16 + pad)

__device__ __half g_bth1[NB * NN];   // layer-1 B, fp16 chunk-permuted
__device__ __half g_bth2[NB * NN];   // layer-1 out (x2^6) = layer-2 B

// chunk permutation within each k32 block (2-element chunks):
// chunk j -> position (j%4)*4 + j/4
__device__ __forceinline__ int kperm2(int k) {
    int j = (k >> 1) & 15;
    int p = ((j & 3) << 2) | (j >> 2);
    return (k & ~31) | (p << 1) | (k & 1);
}

__device__ __forceinline__ uint32_t smem_u32(const void* p) {
    uint32_t a;
    asm("{ .reg .u64 t; cvta.to.shared.u64 t, %1; cvt.u32.u64 %0, t; }"
        : "=r"(a) : "l"(p));
    return a;
}

// pack two fp32 -> fp16x2 (lo = first arg)
__device__ __forceinline__ uint32_t pack_h2(float lo, float hi) {
    uint32_t d;
    asm("cvt.rn.f16x2.f32 %0, %1, %2;" : "=r"(d) : "f"(hi), "f"(lo));
    return d;
}

#define GDC_LAUNCH() asm volatile("griddepcontrol.launch_dependents;" ::: "memory")
#define GDC_WAIT()   asm volatile("griddepcontrol.wait;" ::: "memory")

#define CP_ASYNC16(dst, src) \
    asm volatile("cp.async.cg.shared.global [%0], [%1], 16;" \
                 :: "r"(dst), "l"(src) : "memory")

#define MBAR_INIT(addr, cnt) \
    asm volatile("mbarrier.init.shared.b64 [%0], %1;" :: "r"(addr), "r"(cnt) : "memory")
#define MBAR_ARRIVE(addr) \
    asm volatile("mbarrier.arrive.shared.b64 _, [%0];" :: "r"(addr) : "memory")
#define CP_ASYNC_MBAR_ARRIVE(addr) \
    asm volatile("cp.async.mbarrier.arrive.noinc.shared::cta.b64 [%0];" \
                 :: "r"(addr) : "memory")

#define MBAR_WAIT(addr, parity) do {                                          \
    uint32_t _mb = (addr); uint32_t _ph = (parity); uint32_t _done;           \
    asm volatile("{\n\t.reg .pred p;\n\t"                                     \
        "mbarrier.try_wait.parity.acquire.cta.shared::cta.b64 p, [%1], %2;\n\t"\
        "selp.b32 %0, 1, 0, p;\n\t}"                                          \
        : "=r"(_done) : "r"(_mb), "r"(_ph) : "memory");                       \
    if (!_done) {                                                             \
        asm volatile("{\n\t.reg .pred P1;\n\t"                                \
            "WL_%=:\n\t"                                                      \
            "mbarrier.try_wait.parity.acquire.cta.shared::cta.b64 P1, [%0], %1, 0x989680;\n\t" \
            "@P1 bra.uni WD_%=;\n\t"                                          \
            "bra.uni WL_%=;\n\t"                                              \
            "WD_%=:\n\t}"                                                     \
            :: "r"(_mb), "r"(_ph) : "memory");                                \
    }                                                                         \
} while (0)

__device__ __forceinline__ void mma_f16(float* c, const uint32_t* a,
                                        uint32_t b0, uint32_t b1) {
    asm volatile(
        "mma.sync.aligned.m16n8k16.row.col.f32.f16.f16.f32 "
        "{%0,%1,%2,%3}, {%4,%5,%6,%7}, {%8,%9}, {%0,%1,%2,%3};"
        : "+f"(c[0]), "+f"(c[1]), "+f"(c[2]), "+f"(c[3])
        : "r"(a[0]), "r"(a[1]), "r"(a[2]), "r"(a[3]), "r"(b0), "r"(b1));
}

// ---------------------------------------------------------------------------
__global__ void pack_bt_kernel(const float* __restrict__ F,
                               const float* __restrict__ G,
                               __half* __restrict__ Bt) {
    GDC_LAUNCH();                       // let gemm1 launch + prefetch A early
    __shared__ float tile[32][33];
    int kb = blockIdx.x * 32;
    int nb = blockIdx.y * 32;
    int tx = threadIdx.x, ty = threadIdx.y;   // block (32, 8)
    #pragma unroll
    for (int r = ty; r < 32; r += 8) {
        int k = kb + r, n = nb + tx;
        float v = (n < 64) ? F[(size_t)k * 64 + n] : G[(size_t)k * 64 + (n - 64)];
        tile[r][tx] = v;
    }
    __syncthreads();
    #pragma unroll
    for (int r = ty; r < 32; r += 8) {
        int n = nb + r, k = kb + tx;
        Bt[(size_t)n * NN + kperm2(k)] = __float2half_rn(tile[tx][r]);
    }
}

// ---------------------------------------------------------------------------
__global__ void __launch_bounds__(384, 1)
gemm_layer(const float* __restrict__ A, const __half* __restrict__ Bt,
           __half* __restrict__ outT, float* __restrict__ outR, float scale) {
    extern __shared__ char smem[];
    __shared__ __align__(8) uint64_t mbar[2 * STAGES];

    const int tid  = threadIdx.x;
    const int lane = tid & 31;
    const int w    = tid >> 5;
    const int m0   = blockIdx.x * MT;
    const uint32_t sbase = smem_u32(smem);
    const uint32_t mb    = smem_u32(mbar);
    const int r4 = lane >> 2;
    const int c4 = lane & 3;

    if (tid == 0) {
        #pragma unroll
        for (int s = 0; s < STAGES; s++) {
            MBAR_INIT(mb + 8 * s, 128);                 // full: cp.async x128
            MBAR_INIT(mb + 8 * (STAGES + s), 256);      // empty: 256 consumers
        }
    }
    __syncthreads();
    GDC_LAUNCH();          // allow next kernel's CTAs to start as SMs free up

    if (w >= 8) {
        // ================= producers (warps 8-11) =================
        const int t = tid - 256;

        auto issueA = [&](int it) {
            const int k0 = it * KT;
            const uint32_t abase = sbase + (uint32_t)(it & (STAGES - 1)) * STG_B;
            #pragma unroll
            for (int j = 0; j < 4; j++) {               // A: 512 x 16B (fp32)
                int ch = t + 128 * j;
                int row = ch >> 3, cc = ch & 7;
                const float* src = A + (size_t)(m0 + row) * NN + k0 + cc * 4;
                CP_ASYNC16(abase + (uint32_t)(row * A_PITCH + cc * 16), src);
            }
        };
        auto issueB = [&](int it) {
            const int k0 = it * KT;
            const uint32_t bbase = sbase + (uint32_t)(it & (STAGES - 1)) * STG_B
                                   + A_STG_B;
            #pragma unroll
            for (int j = 0; j < 4; j++) {               // B: 512 x 16B (fp16)
                int ch = t + 128 * j;
                int col = ch >> 2, q = ch & 3;
                const __half* src = Bt + (size_t)col * NN + k0 + q * 8;
                CP_ASYNC16(bbase + (uint32_t)(col * B_PITCH + q * 16), src);
            }
        };

        // A-only prefetch (no dependency on previous kernel's output)
        issueA(0); issueA(1); issueA(2);
        GDC_WAIT();                     // previous kernel's Bt now visible
        #pragma unroll
        for (int it = 0; it < 3; it++) {
            issueB(it);
            CP_ASYNC_MBAR_ARRIVE(mb + 8 * it);
        }
        for (int it = 3; it < KIT; it++) {
            const int s = it & (STAGES - 1);
            const int r = it >> 3;
            if (r > 0) MBAR_WAIT(mb + 8 * (STAGES + s), (r - 1) & 1);
            issueA(it);
            issueB(it);
            CP_ASYNC_MBAR_ARRIVE(mb + 8 * s);
        }
        return;
    }

    // ========== MMA warps (0-7): 32 rows x 32 cols, 2 per SMSP ==========
    const int wm = w & 1;        // rows wm*32 .. +31
    const int wn = w >> 1;       // cols wn*32 .. +31

    float acc[2][4][4];
    #pragma unroll
    for (int mi = 0; mi < 2; mi++)
        #pragma unroll
        for (int ni = 0; ni < 4; ni++)
            #pragma unroll
            for (int j = 0; j < 4; j++) acc[mi][ni][j] = 0.f;

    const uint32_t aoff = (uint32_t)((wm * 32 + r4) * A_PITCH + 8 * c4);
    const uint32_t boff = (uint32_t)((wn * 32 + r4) * B_PITCH + 16 * c4);

    // A half h (k16) of stage s -> 8 fp16x2 regs (scaled x2^13)
    auto loadA = [&](int s, int h, uint32_t (&aH)[4][2]) {
        const uint32_t off = (uint32_t)s * STG_B + aoff + (uint32_t)(h * 64);
        #pragma unroll
        for (int g = 0; g < 4; g++) {
            float2 lo = *(const float2*)(smem + off + g * 8 * A_PITCH);
            float2 hi = *(const float2*)(smem + off + g * 8 * A_PITCH + 32);
            aH[g][0] = pack_h2(lo.x * 8192.f, lo.y * 8192.f);
            aH[g][1] = pack_h2(hi.x * 8192.f, hi.y * 8192.f);
        }
    };

    // warp's 32-col B slice of a stage -> 4 x uint4 (x=h0b0,y=h0b1,z=h1b0,w=h1b1)
    auto loadB = [&](int s, uint4 (&bS)[4]) {
        const char* base = smem + (size_t)s * STG_B + A_STG_B + boff;
        #pragma unroll
        for (int g = 0; g < 4; g++)
            bS[g] = *(const uint4*)(base + g * 8 * B_PITCH);
    };

    auto mma_half = [&](uint32_t (&aH)[4][2], uint4 (&bS)[4], int h) {
        #pragma unroll
        for (int ni = 0; ni < 4; ni++) {
            uint32_t b0 = h ? bS[ni].z : bS[ni].x;
            uint32_t b1 = h ? bS[ni].w : bS[ni].y;
            {
                uint32_t af[4] = { aH[0][0], aH[1][0], aH[0][1], aH[1][1] };
                mma_f16(acc[0][ni], af, b0, b1);
            }
            {
                uint32_t af[4] = { aH[2][0], aH[3][0], aH[2][1], aH[3][1] };
                mma_f16(acc[1][ni], af, b0, b1);
            }
        }
    };

    uint32_t A0[4][2], A1[4][2];
    uint4    Bb[2][4];

    MBAR_WAIT(mb + 0, 0);
    loadB(0, Bb[0]);
    loadA(0, 0, A0);

    #pragma unroll 2
    for (int it = 0; it < KIT; it++) {
        const int s = it & (STAGES - 1);
        const int cur = it & 1, nxt = cur ^ 1;

        loadA(s, 1, A1);
        mma_half(A0, Bb[cur], 0);

        if (it + 1 < KIT) {
            const int s1 = (it + 1) & (STAGES - 1);
            MBAR_WAIT(mb + 8 * s1, ((it + 1) >> 3) & 1);
            loadB(s1, Bb[nxt]);
            loadA(s1, 0, A0);
        }
        mma_half(A1, Bb[cur], 1);

        MBAR_ARRIVE(mb + 8 * (STAGES + s));
    }

    // ---- epilogue ----
    const int rBase = m0 + wm * 32 + r4;
    const int cBase = wn * 32 + c4 * 2;

    if (outT) {
        // staged transposed store: smem [col][row] (pitch 136B), then each
        // warp streams 16 cols as coalesced 4B lane stores.
        asm volatile("bar.sync 1, 256;" ::: "memory");   // all MMAs done
        #pragma unroll
        for (int mi = 0; mi < 2; mi++) {
            #pragma unroll
            for (int ni = 0; ni < 4; ni++) {
                #pragma unroll
                for (int j = 0; j < 4; j++) {
                    int row_l = wm * 32 + r4 + mi * 16 + (j >> 1) * 8;
                    int col   = cBase + ni * 8 + (j & 1);
                    float v = acc[mi][ni][j] * scale;
                    if (col < 64) v = fmaxf(v, 0.0f);
                    *(__half*)(smem + col * STG_PITCH + row_l * 2) =
                        __float2half_rn(v);
                }
            }
        }
        asm volatile("bar.sync 1, 256;" ::: "memory");
        const int b  = lane >> 4;
        const int jj = lane & 15;
        const int q  = ((jj & 3) << 2) | (jj >> 2);     // kperm2 chunk pos
        #pragma unroll
        for (int c = 0; c < 16; c++) {
            int col = w * 16 + c;
            uint32_t v = *(const uint32_t*)(smem + col * STG_PITCH + lane * 4);
            *(uint32_t*)((char*)outT +
                2 * ((size_t)col * NN + m0 + b * 32 + 2 * q)) = v;
        }
    } else {
        #pragma unroll
        for (int mi = 0; mi < 2; mi++) {
            #pragma unroll
            for (int ni = 0; ni < 4; ni++) {
                #pragma unroll
                for (int jh = 0; jh < 2; jh++) {
                    int row = rBase + mi * 16 + jh * 8;
                    int col = cBase + ni * 8;
                    float v0 = acc[mi][ni][2 * jh]     * scale;
                    float v1 = acc[mi][ni][2 * jh + 1] * scale;
                    if (col < 64) { v0 = fmaxf(v0, 0.f); v1 = fmaxf(v1, 0.f); }
                    *(float2*)(outR + (size_t)row * NB + col) =
                        make_float2(v0, v1);
                }
            }
        }
    }
}

// ---------------------------------------------------------------------------
extern "C" void kernel_launch(void* const* d_in, const int* in_sizes, int n_in,
                              void* d_out, int out_size) {
    (void)in_sizes; (void)n_in; (void)out_size;
    const float* A = (const float*)d_in[0];
    const float* F = (const float*)d_in[1];
    const float* G = (const float*)d_in[2];
    float* out = (float*)d_out;

    __half *bt1 = nullptr, *bt2 = nullptr;
    cudaGetSymbolAddress((void**)&bt1, g_bth1);
    cudaGetSymbolAddress((void**)&bt2, g_bth2);

    cudaFuncSetAttribute(gemm_layer,
                         cudaFuncAttributeMaxDynamicSharedMemorySize, SMEM_BYTES);

    dim3 pb(32, 8), pg(NN / 32, NB / 32);
    pack_bt_kernel<<<pg, pb>>>(F, G, bt1);

    cudaLaunchAttribute at[1];
    at[0].id = cudaLaunchAttributeProgrammaticStreamSerialization;
    at[0].val.programmaticStreamSerializationAllowed = 1;

    cudaLaunchConfig_t cfg = {};
    cfg.gridDim = dim3(NN / MT);
    cfg.blockDim = dim3(384);
    cfg.dynamicSmemBytes = SMEM_BYTES;
    cfg.stream = 0;
    cfg.attrs = at;
    cfg.numAttrs = 1;

    // layer 1: acc = (2^13 A) @ B ; store fp16( acc * 2^-7 ) = 2^6 * (A@B)
    cudaError_t e1 = cudaLaunchKernelEx(&cfg, gemm_layer,
                                        A, (const __half*)bt1, bt2,
                                        (float*)nullptr, 0.0078125f);
    if (e1 != cudaSuccess)
        gemm_layer<<<NN / MT, 384, SMEM_BYTES>>>(A, bt1, bt2, nullptr,
                                                 0.0078125f);

    // layer 2: acc = (2^13 A) @ (2^6 h) ; out = acc * 2^-19
    cudaError_t e2 = cudaLaunchKernelEx(&cfg, gemm_layer,
                                        A, (const __half*)bt2, (__half*)nullptr,
                                        out, 1.0f / 524288.0f);
    if (e2 != cudaSuccess)
        gemm_layer<<<NN / MT, 384, SMEM_BYTES>>>(A, bt2, nullptr, out,
                                                 1.0f / 524288.0f);
}